// round 7
// baseline (speedup 1.0000x reference)
#include <cuda_runtime.h>
#include <cuda_bf16.h>
#include <cstdint>
#include <math.h>

#define N_NODES 30000
#define DIM     128
#define T_LINKS 3000
#define K_NEG   75
#define NQ      (2 * T_LINKS)
#define EPSF    1e-7f
#define MAXSQ   50.0f
#define GAMMA   1.0f

#define WARPS_PER_BLOCK 8
#define NB (NQ / WARPS_PER_BLOCK)   // 750 blocks, 8 queries per block
#define TILE 64                      // candidates per smem tile (bf16)
#define NTILES 4                     // fixed screen: 256 candidates
#define ROWW 68                      // uint32 words per bf16 row (64 data + 4 pad)

// ---------------- scratch (no device allocations allowed) ----------------
__device__ float        g_partial[NB];
__device__ unsigned int g_ticket = 0;

static __device__ __forceinline__ unsigned int pack_bf(float a, float b) {
    __nv_bfloat162 h = __floats2bfloat162_rn(a, b);
    return *reinterpret_cast<unsigned int*>(&h);
}
static __device__ __forceinline__ __nv_bfloat162 u2b(unsigned int w) {
    return *reinterpret_cast<__nv_bfloat162*>(&w);
}

// Math: sq(prod) = min(K*acosh(max(-prod*c,1+eps))^2, 50) is weakly monotone
// non-increasing in prod => the 75 smallest distances are the 75 largest
// Minkowski prods. With emb ~ N(0,1), ~16000/30000 candidates clip to
// theta = 1+eps (the global minimum sq_min), so the 75 nearest all have
// sq == sq_min exactly and the row contribution is 75*relu(D - sq_min).
// We screen a fixed 256 candidates in bf16 (counts ~135 >> 75; bf16 noise
// flips only ~3 near-threshold candidates — the screen only *selects* the
// formula, never contributes a value). Exact fp32 lexicographic top-75
// fallback guarantees correctness if any query screens < 75.
__global__ void __launch_bounds__(256, 6)
fused_kernel(const float* __restrict__ emb,
             const float* __restrict__ cptr,
             const void*  __restrict__ links,
             float* __restrict__ out) {
    __shared__ __align__(16) unsigned int s_cand[2][TILE][ROWW];    // 34816 B
    __shared__ __align__(16) unsigned int s_q[WARPS_PER_BLOCK][ROWW]; // 2176 B
    __shared__ int   s_qcnt[WARPS_PER_BLOCK];
    __shared__ float s_wsum[WARPS_PER_BLOCK];
    __shared__ int   s_islast;

    const int t    = threadIdx.x;
    const int wid  = t >> 5;
    const int lane = t & 31;
    const int bid  = blockIdx.x;

    // ---- link dtype detection (int64-LE with values<30000 => odd words 0) ----
    int loc = 0;
    {
        const int* w = (const int*)links;
        for (int i = t; i < T_LINKS; i += 256)
            if (w[2 * i + 1] != 0) loc = 1;
    }
    if (t < WARPS_PER_BLOCK) s_qcnt[t] = 0;
    const int is64 = !__syncthreads_or(loc);

    // ---- per-warp query setup (warp w owns query w of this block) ----
    const int gwarp = bid * WARPS_PER_BLOCK + wid;
    const int li    = gwarp % T_LINKS;
    const int side  = gwarp / T_LINKS;          // 0 = left query, 1 = right

    int l, r;
    if (is64) {
        const long long* p = (const long long*)links;
        l = (int)p[2 * li]; r = (int)p[2 * li + 1];
    } else {
        const int* p = (const int*)links;
        l = p[2 * li]; r = p[2 * li + 1];
    }

    const float c  = cptr[0];
    const float K  = 1.0f / c;
    const float thr_theta = 1.0f + EPSF;        // rounds to 1+2^-23, same as jax fp32
    const float prod_thr  = -thr_theta * K;     // clipped  <=>  prod >= prod_thr
    float acm = acoshf(thr_theta);
    const float sq_min = fminf(K * acm * acm, MAXSQ);

    const float4* E4 = (const float4*)emb;

    // ---- D = sqdist(left, right) + GAMMA (fp32 exact, one-time butterfly) ----
    float4 lv = E4[(size_t)l * (DIM / 4) + lane];
    float4 rv = E4[(size_t)r * (DIM / 4) + lane];
    float pd = lv.x * rv.x + lv.y * rv.y + lv.z * rv.z + lv.w * rv.w;
    if (lane == 0) pd -= 2.0f * lv.x * rv.x;    // Minkowski: -x0*y0
    #pragma unroll
    for (int o = 16; o; o >>= 1) pd += __shfl_xor_sync(0xffffffffu, pd, o);
    float th = fmaxf(-pd * c, thr_theta);
    float ac = acoshf(th);
    const float D = fminf(K * ac * ac, MAXSQ) + GAMMA;

    // ---- stage query into smem as bf16x2 (dim0 negated: plain dot == Minkowski) ----
    const int qrow = (side == 0) ? l : r;
    {
        float4 qv = E4[(size_t)qrow * (DIM / 4) + lane];
        if (lane == 0) qv.x = -qv.x;
        uint2 w;
        w.x = pack_bf(qv.x, qv.y);
        w.y = pack_bf(qv.z, qv.w);
        *(uint2*)&s_q[wid][lane * 2] = w;
    }

    // ---- lane roles for the screen ----
    const int my_query = lane & 7;
    const unsigned int* qr = &s_q[my_query][0];
    int cnt = 0;

    // ---- stage tile 0 ----
    #pragma unroll
    for (int k = 0; k < 4; ++k) {
        int idx = t + (k << 8);
        int row = idx >> 4, q4 = idx & 15;
        float4 f0 = E4[(size_t)row * (DIM / 4) + 2 * q4];
        float4 f1 = E4[(size_t)row * (DIM / 4) + 2 * q4 + 1];
        uint4 w;
        w.x = pack_bf(f0.x, f0.y); w.y = pack_bf(f0.z, f0.w);
        w.z = pack_bf(f1.x, f1.y); w.w = pack_bf(f1.z, f1.w);
        *(uint4*)&s_cand[0][row][q4 << 2] = w;
    }
    __syncthreads();

    // ---- fixed 4-tile screen, double-buffered ----
    #pragma unroll
    for (int tile = 0; tile < NTILES; ++tile) {
        const int buf = tile & 1;
        if (tile < NTILES - 1) {
            const int nb = buf ^ 1, base = (tile + 1) * TILE;
            #pragma unroll
            for (int k = 0; k < 4; ++k) {
                int idx = t + (k << 8);
                int row = idx >> 4, q4 = idx & 15;
                float4 f0 = E4[(size_t)(base + row) * (DIM / 4) + 2 * q4];
                float4 f1 = E4[(size_t)(base + row) * (DIM / 4) + 2 * q4 + 1];
                uint4 w;
                w.x = pack_bf(f0.x, f0.y); w.y = pack_bf(f0.z, f0.w);
                w.z = pack_bf(f1.x, f1.y); w.w = pack_bf(f1.z, f1.w);
                *(uint4*)&s_cand[nb][row][q4 << 2] = w;
            }
        }
        // two passes: warp covers candidates 4w..4w+3 (+32 on pass 1), 8 queries
        #pragma unroll
        for (int pass = 0; pass < 2; ++pass) {
            const unsigned int* cr =
                &s_cand[buf][(pass << 5) + (wid << 2) + (lane >> 3)][0];
            __nv_bfloat162 a0 = __float2bfloat162_rn(0.f);
            __nv_bfloat162 a1 = a0, a2 = a0, a3 = a0;
            #pragma unroll
            for (int i = 0; i < 16; ++i) {
                uint4 av = *(const uint4*)&cr[i << 2];
                uint4 bv = *(const uint4*)&qr[i << 2];
                a0 = __hfma2(u2b(av.x), u2b(bv.x), a0);
                a1 = __hfma2(u2b(av.y), u2b(bv.y), a1);
                a2 = __hfma2(u2b(av.z), u2b(bv.z), a2);
                a3 = __hfma2(u2b(av.w), u2b(bv.w), a3);
            }
            float2 f0 = __bfloat1622float2(a0);
            float2 f1 = __bfloat1622float2(a1);
            float2 f2 = __bfloat1622float2(a2);
            float2 f3 = __bfloat1622float2(a3);
            float total = (f0.x + f0.y) + (f1.x + f1.y)
                        + (f2.x + f2.y) + (f3.x + f3.y);
            cnt += (total >= prod_thr);
        }
        __syncthreads();
    }

    // ---- per-query counts: 4-lane groups {q,q+8,q+16,q+24} share a query ----
    cnt += __shfl_xor_sync(0xffffffffu, cnt, 8);
    cnt += __shfl_xor_sync(0xffffffffu, cnt, 16);
    if (lane < WARPS_PER_BLOCK && cnt) atomicAdd(&s_qcnt[lane], cnt);
    __syncthreads();

    // ---- per-warp contribution (warp w -> query w) ----
    float contrib;
    if (s_qcnt[wid] >= K_NEG) {
        contrib = (float)K_NEG * fmaxf(D - sq_min, 0.0f);
    } else {
        // exact fp32 fallback: top-75 largest (prod, -idx), lexicographic
        const float* q = emb + (size_t)qrow * DIM;
        float prevP = INFINITY; int prevI = -1;
        float s = 0.0f;
        for (int pick = 0; pick < K_NEG; ++pick) {
            float bp = -INFINITY; int bi = 0x7fffffff;
            for (int j = lane; j < N_NODES; j += 32) {
                const float* e = emb + (size_t)j * DIM;
                float p = -q[0] * e[0];
                #pragma unroll 8
                for (int d = 1; d < DIM; ++d) p += q[d] * e[d];
                bool after = (p < prevP) || (p == prevP && j > prevI);
                if (after && (p > bp || (p == bp && j < bi))) { bp = p; bi = j; }
            }
            #pragma unroll
            for (int o = 16; o; o >>= 1) {
                float op = __shfl_xor_sync(0xffffffffu, bp, o);
                int   oi = __shfl_xor_sync(0xffffffffu, bi, o);
                if (op > bp || (op == bp && oi < bi)) { bp = op; bi = oi; }
            }
            prevP = bp; prevI = bi;
            float t2 = fmaxf(-bp * c, thr_theta);
            float a2 = acoshf(t2);
            float sq = fminf(K * a2 * a2, MAXSQ);
            s += fmaxf(D - sq, 0.0f);
        }
        contrib = s;
    }

    if (lane == 0) s_wsum[wid] = contrib;
    __syncthreads();

    // ---- block sum -> partial, last-block-done final reduction ----
    if (t == 0) {
        float bs = 0.0f;
        #pragma unroll
        for (int w = 0; w < WARPS_PER_BLOCK; ++w) bs += s_wsum[w];
        g_partial[bid] = bs;
        __threadfence();
        unsigned old = atomicInc(&g_ticket, NB - 1);  // wraps to 0 for replays
        s_islast = (old == NB - 1);
    }
    __syncthreads();

    if (s_islast) {
        float* rsm = (float*)&s_cand[0][0][0];        // reuse tile smem
        float s = 0.0f;
        for (int i = t; i < NB; i += 256) s += g_partial[i];
        rsm[t] = s;
        __syncthreads();
        #pragma unroll
        for (int o = 128; o; o >>= 1) {
            if (t < o) rsm[t] += rsm[t + o];
            __syncthreads();
        }
        if (t == 0)
            out[0] = rsm[0] / (2.0f * (float)K_NEG * (float)T_LINKS);
    }
}

extern "C" void kernel_launch(void* const* d_in, const int* in_sizes, int n_in,
                              void* d_out, int out_size) {
    const float* emb   = (const float*)d_in[0];
    const float* cptr  = (const float*)d_in[1];
    const void*  links = d_in[2];

    fused_kernel<<<NB, 256>>>(emb, cptr, links, (float*)d_out);
}

// round 8
// speedup vs baseline: 1.9258x; 1.9258x over previous
#include <cuda_runtime.h>
#include <cstdint>
#include <math.h>

#define N_NODES 30000
#define DIM     128
#define T_LINKS 3000
#define K_NEG   75
#define NQ      (2 * T_LINKS)
#define EPSF    1e-7f
#define MAXSQ   50.0f
#define GAMMA   1.0f

#define WARPS_PER_BLOCK 8
#define NB (NQ / WARPS_PER_BLOCK)    // 750 blocks, 8 queries per block
#define CHUNK 64                      // candidates between early-exit checks
#define NCHUNKS ((N_NODES + CHUNK - 1) / CHUNK)
#define ROWF 132                      // padded query row stride (floats)

// ---------------- scratch (no device allocations allowed) ----------------
__device__ float        g_partial[NB];
__device__ unsigned int g_ticket = 0;

// Math: sq(prod) = min(K*acosh(max(-prod*c,1+eps))^2, 50) is weakly monotone
// non-increasing in prod => the 75 smallest distances are the 75 largest
// Minkowski prods. With emb ~ N(0,1), ~16000/30000 candidates clip to
// theta = 1+eps (the global minimum sq_min), so the 75 nearest all have
// sq == sq_min exactly and the row contribution is 75*relu(D - sq_min).
// We count clipped candidates with chunked early exit (~165 rows scanned, all
// L1-resident). Lane = (candidate, query) pair: each candidate GMEM read is
// an 8-lane broadcast serving 8 queries. Exact fp32 lexicographic top-75
// fallback guarantees correctness if any query ends with count < 75.
__global__ void __launch_bounds__(256)
fused_kernel(const float* __restrict__ emb,
             const float* __restrict__ cptr,
             const void*  __restrict__ links,
             float* __restrict__ out) {
    __shared__ float s_q[WARPS_PER_BLOCK][ROWF];   // 4224 B
    __shared__ float s_red[256];                    // 1024 B (final reduce)
    __shared__ int   s_qcnt[WARPS_PER_BLOCK];
    __shared__ float s_wsum[WARPS_PER_BLOCK];
    __shared__ int   s_islast;

    const int t    = threadIdx.x;
    const int wid  = t >> 5;
    const int lane = t & 31;
    const int bid  = blockIdx.x;

    // ---- link dtype detection (int64-LE with values<30000 => odd words 0) ----
    int loc = 0;
    {
        const int* w = (const int*)links;
        for (int i = t; i < T_LINKS; i += 256)
            if (w[2 * i + 1] != 0) loc = 1;
    }
    if (t < WARPS_PER_BLOCK) s_qcnt[t] = 0;
    const int is64 = !__syncthreads_or(loc);   // also publishes s_qcnt init

    // ---- per-warp query setup (warp w owns query w of this block) ----
    const int gwarp = bid * WARPS_PER_BLOCK + wid;
    const int li    = gwarp % T_LINKS;
    const int side  = gwarp / T_LINKS;         // 0 = left query, 1 = right

    int l, r;
    if (is64) {
        const long long* p = (const long long*)links;
        l = (int)p[2 * li]; r = (int)p[2 * li + 1];
    } else {
        const int* p = (const int*)links;
        l = p[2 * li]; r = p[2 * li + 1];
    }

    const float c  = cptr[0];
    const float K  = 1.0f / c;
    const float thr_theta = 1.0f + EPSF;       // rounds to 1+2^-23, same as jax fp32
    const float prod_thr  = -thr_theta * K;    // clipped  <=>  prod >= prod_thr
    float acm = acoshf(thr_theta);
    const float sq_min = fminf(K * acm * acm, MAXSQ);

    const float4* E4 = (const float4*)emb;

    // ---- D = sqdist(left, right) + GAMMA (fp32 exact, one-time butterfly) ----
    float4 lv = E4[(size_t)l * (DIM / 4) + lane];
    float4 rv = E4[(size_t)r * (DIM / 4) + lane];
    float pd = lv.x * rv.x + lv.y * rv.y + lv.z * rv.z + lv.w * rv.w;
    if (lane == 0) pd -= 2.0f * lv.x * rv.x;   // Minkowski: -x0*y0
    #pragma unroll
    for (int o = 16; o; o >>= 1) pd += __shfl_xor_sync(0xffffffffu, pd, o);
    float th = fmaxf(-pd * c, thr_theta);
    float ac = acoshf(th);
    const float D = fminf(K * ac * ac, MAXSQ) + GAMMA;

    // ---- stage query into smem (dim0 negated so plain dot == Minkowski) ----
    const int qrow = (side == 0) ? l : r;
    {
        float4 qv = E4[(size_t)qrow * (DIM / 4) + lane];
        if (lane == 0) qv.x = -qv.x;
        *(float4*)&s_q[wid][lane * 4] = qv;
    }
    __syncthreads();                            // queries visible to all warps

    // ---- lane roles: cand-group = wid*4 + lane/8, query = lane&7 ----
    const int cand_off = (wid << 2) + (lane >> 3);   // 0..31 within 32-chunk
    const int my_query = lane & 7;
    const float4* qr = (const float4*)&s_q[my_query][0];

    // ---- chunked scan with early exit; candidates straight from L1 ----
    int cnt = 0;
    for (int chunk = 0; chunk < NCHUNKS; ++chunk) {
        const int base = chunk * CHUNK;
        #pragma unroll
        for (int sub = 0; sub < 2; ++sub) {
            const int cand = base + (sub << 5) + cand_off;
            const float4* cr = E4 + (size_t)min(cand, N_NODES - 1) * (DIM / 4);
            float a0 = 0.f, a1 = 0.f, a2 = 0.f, a3 = 0.f;
            #pragma unroll
            for (int i = 0; i < DIM / 4; i += 4) {
                float4 c0 = __ldg(cr + i);
                float4 c1 = __ldg(cr + i + 1);
                float4 c2 = __ldg(cr + i + 2);
                float4 c3 = __ldg(cr + i + 3);
                float4 q0 = qr[i];
                float4 q1 = qr[i + 1];
                float4 q2 = qr[i + 2];
                float4 q3 = qr[i + 3];
                a0 += c0.x * q0.x + c0.y * q0.y + c0.z * q0.z + c0.w * q0.w;
                a1 += c1.x * q1.x + c1.y * q1.y + c1.z * q1.z + c1.w * q1.w;
                a2 += c2.x * q2.x + c2.y * q2.y + c2.z * q2.z + c2.w * q2.w;
                a3 += c3.x * q3.x + c3.y * q3.y + c3.z * q3.z + c3.w * q3.w;
            }
            float total = (a0 + a1) + (a2 + a3);
            cnt += (cand < N_NODES) && (total >= prod_thr);
        }
        // per-query partial: lanes {q, q+8, q+16, q+24} share query q
        int pc = cnt;
        pc += __shfl_xor_sync(0xffffffffu, pc, 8);
        pc += __shfl_xor_sync(0xffffffffu, pc, 16);
        if (lane < WARPS_PER_BLOCK && pc) atomicAdd(&s_qcnt[lane], pc);
        cnt = 0;
        __syncthreads();                        // all adds for this chunk done
        int4 c0 = *(const int4*)&s_qcnt[0];
        int4 c1 = *(const int4*)&s_qcnt[4];
        int mn = min(min(min(c0.x, c0.y), min(c0.z, c0.w)),
                     min(min(c1.x, c1.y), min(c1.z, c1.w)));
        __syncthreads();                        // checks done before next adds
        if (mn >= K_NEG) break;                 // block-uniform
    }

    // ---- per-warp contribution (warp w -> query w) ----
    float contrib;
    if (s_qcnt[wid] >= K_NEG) {
        contrib = (float)K_NEG * fmaxf(D - sq_min, 0.0f);
    } else {
        // exact fp32 fallback: top-75 largest (prod, -idx), lexicographic
        const float* q = emb + (size_t)qrow * DIM;
        float prevP = INFINITY; int prevI = -1;
        float s = 0.0f;
        for (int pick = 0; pick < K_NEG; ++pick) {
            float bp = -INFINITY; int bi = 0x7fffffff;
            for (int j = lane; j < N_NODES; j += 32) {
                const float* e = emb + (size_t)j * DIM;
                float p = -q[0] * e[0];
                #pragma unroll 8
                for (int d = 1; d < DIM; ++d) p += q[d] * e[d];
                bool after = (p < prevP) || (p == prevP && j > prevI);
                if (after && (p > bp || (p == bp && j < bi))) { bp = p; bi = j; }
            }
            #pragma unroll
            for (int o = 16; o; o >>= 1) {
                float op = __shfl_xor_sync(0xffffffffu, bp, o);
                int   oi = __shfl_xor_sync(0xffffffffu, bi, o);
                if (op > bp || (op == bp && oi < bi)) { bp = op; bi = oi; }
            }
            prevP = bp; prevI = bi;
            float t2 = fmaxf(-bp * c, thr_theta);
            float a2 = acoshf(t2);
            float sq = fminf(K * a2 * a2, MAXSQ);
            s += fmaxf(D - sq, 0.0f);
        }
        contrib = s;
    }

    if (lane == 0) s_wsum[wid] = contrib;
    __syncthreads();

    // ---- block sum -> partial, last-block-done final reduction ----
    if (t == 0) {
        float bs = 0.0f;
        #pragma unroll
        for (int w = 0; w < WARPS_PER_BLOCK; ++w) bs += s_wsum[w];
        g_partial[bid] = bs;
        __threadfence();
        unsigned old = atomicInc(&g_ticket, NB - 1);  // wraps to 0 for replays
        s_islast = (old == NB - 1);
    }
    __syncthreads();

    if (s_islast) {
        float s = 0.0f;
        for (int i = t; i < NB; i += 256) s += g_partial[i];
        s_red[t] = s;
        __syncthreads();
        #pragma unroll
        for (int o = 128; o; o >>= 1) {
            if (t < o) s_red[t] += s_red[t + o];
            __syncthreads();
        }
        if (t == 0)
            out[0] = s_red[0] / (2.0f * (float)K_NEG * (float)T_LINKS);
    }
}

extern "C" void kernel_launch(void* const* d_in, const int* in_sizes, int n_in,
                              void* d_out, int out_size) {
    const float* emb   = (const float*)d_in[0];
    const float* cptr  = (const float*)d_in[1];
    const void*  links = d_in[2];

    fused_kernel<<<NB, 256>>>(emb, cptr, links, (float*)d_out);
}

// round 9
// speedup vs baseline: 3.7737x; 1.9595x over previous
#include <cuda_runtime.h>
#include <cuda_bf16.h>
#include <cstdint>
#include <math.h>

#define N_NODES 30000
#define DIM     128
#define T_LINKS 3000
#define K_NEG   75
#define NQ      (2 * T_LINKS)
#define EPSF    1e-7f
#define MAXSQ   50.0f
#define GAMMA   1.0f

#define QPB   16                      // queries per block
#define NB    (NQ / QPB)              // 375 blocks
#define TILE  64                      // candidates per smem tile (bf16)
#define NTILES 4                      // fixed screen: 256 candidates
#define ROWW  68                      // uint32 words per bf16 row (64 data + 4 pad)
#define SCREEN_MARGIN 0.5f            // stricter screen: only under-counts

// ---------------- scratch (no device allocations allowed) ----------------
__device__ float        g_partial[NB];
__device__ unsigned int g_ticket = 0;

static __device__ __forceinline__ unsigned int pack_bf(float a, float b) {
    __nv_bfloat162 h = __floats2bfloat162_rn(a, b);
    return *reinterpret_cast<unsigned int*>(&h);
}
static __device__ __forceinline__ __nv_bfloat162 u2b(unsigned int w) {
    return *reinterpret_cast<__nv_bfloat162*>(&w);
}
static __device__ __forceinline__ float bsum(__nv_bfloat162 a, __nv_bfloat162 b,
                                             __nv_bfloat162 c, __nv_bfloat162 d) {
    float2 f0 = __bfloat1622float2(a), f1 = __bfloat1622float2(b);
    float2 f2 = __bfloat1622float2(c), f3 = __bfloat1622float2(d);
    return ((f0.x + f0.y) + (f1.x + f1.y)) + ((f2.x + f2.y) + (f3.x + f3.y));
}

// Math: sq(prod) = min(K*acosh(max(-prod*c,1+eps))^2, 50) is weakly monotone
// non-increasing in prod => the 75 smallest distances are the 75 largest
// Minkowski prods. With emb ~ N(0,1), ~16000/30000 candidates clip to
// theta = 1+eps (global minimum sq_min), so the 75 nearest all have
// sq == sq_min exactly and the row contribution is 75*relu(D - sq_min).
// Screen: fixed 256 candidates in bf16 with a +0.5 stricter threshold
// (hits ~132 >> 75; stricter threshold means bf16 noise can only UNDER-count,
// and under-count falls to the exact fp32 fallback -> always correct).
// Layout: lane computes 4 dots (2 cands x 2 queries) so each LDS.128 feeds
// two FMA chains; warp covers 16 cands x 8 queries.
__global__ void __launch_bounds__(256, 3)
fused_kernel(const float* __restrict__ emb,
             const float* __restrict__ cptr,
             const void*  __restrict__ links,
             float* __restrict__ out) {
    __shared__ __align__(16) unsigned int s_cand[TILE][ROWW];  // 17408 B
    __shared__ __align__(16) unsigned int s_q[QPB][ROWW];      //  4352 B
    __shared__ float s_D[QPB];
    __shared__ int   s_qrow[QPB];
    __shared__ int   s_qcnt[QPB];
    __shared__ float s_wsum[8];
    __shared__ float s_red[256];
    __shared__ int   s_islast;

    const int t    = threadIdx.x;
    const int wid  = t >> 5;
    const int lane = t & 31;
    const int bid  = blockIdx.x;

    // ---- link dtype detection (int64-LE with values<30000 => odd words 0) ----
    int loc = 0;
    {
        const int* w = (const int*)links;
        for (int i = t; i < T_LINKS; i += 256)
            if (w[2 * i + 1] != 0) loc = 1;
    }
    if (t < QPB) s_qcnt[t] = 0;
    const int is64 = !__syncthreads_or(loc);

    const float c  = cptr[0];
    const float K  = 1.0f / c;
    const float thr_theta = 1.0f + EPSF;     // rounds to 1+2^-23, same as jax fp32
    const float prod_thr  = -thr_theta * K;  // exact clip threshold
    const float scr_thr   = prod_thr + SCREEN_MARGIN;
    float acm = acoshf(thr_theta);
    const float sq_min = fminf(K * acm * acm, MAXSQ);

    const float4* E4 = (const float4*)emb;

    // ---- per-warp setup: warp w owns queries 2w, 2w+1 ----
    #pragma unroll
    for (int j = 0; j < 2; ++j) {
        const int q  = 2 * wid + j;               // 0..15
        const int gq = bid * QPB + q;
        const int li   = gq % T_LINKS;
        const int side = gq / T_LINKS;
        int l, r;
        if (is64) {
            const long long* p = (const long long*)links;
            l = (int)p[2 * li]; r = (int)p[2 * li + 1];
        } else {
            const int* p = (const int*)links;
            l = p[2 * li]; r = p[2 * li + 1];
        }
        // D = sqdist(left,right) + GAMMA (fp32 exact)
        float4 lv = E4[(size_t)l * (DIM / 4) + lane];
        float4 rv = E4[(size_t)r * (DIM / 4) + lane];
        float pd = lv.x * rv.x + lv.y * rv.y + lv.z * rv.z + lv.w * rv.w;
        if (lane == 0) pd -= 2.0f * lv.x * rv.x;  // Minkowski: -x0*y0
        #pragma unroll
        for (int o = 16; o; o >>= 1) pd += __shfl_xor_sync(0xffffffffu, pd, o);
        float th = fmaxf(-pd * c, thr_theta);
        float ac = acoshf(th);
        const int qrow = (side == 0) ? l : r;
        if (lane == 0) {
            s_D[q]    = fminf(K * ac * ac, MAXSQ) + GAMMA;
            s_qrow[q] = qrow;
        }
        // stage query row as bf16 (dim0 negated: plain dot == Minkowski dot)
        float4 qv = E4[(size_t)qrow * (DIM / 4) + lane];
        if (lane == 0) qv.x = -qv.x;
        uint2 w2; w2.x = pack_bf(qv.x, qv.y); w2.y = pack_bf(qv.z, qv.w);
        *(uint2*)&s_q[q][lane * 2] = w2;
    }

    // ---- lane roles: 2 cands x 2 queries per lane ----
    const int qsel = lane & 3;               // query pair: 2*qsel, 2*qsel+1
    const int csel = lane >> 2;              // cand slots: csel, csel+8
    const int qg   = (wid >> 2) * 8;         // query group base (0 or 8)
    const int cg   = (wid & 3) * 16;         // cand group base within tile
    const unsigned int* q0r = &s_q[qg + 2 * qsel][0];
    const unsigned int* q1r = &s_q[qg + 2 * qsel + 1][0];
    const unsigned int* c0r = &s_cand[cg + csel][0];
    const unsigned int* c1r = &s_cand[cg + csel + 8][0];

    int cnt_q0 = 0, cnt_q1 = 0;

    // ---- fixed 4-tile screen, single-buffered ----
    for (int tile = 0; tile < NTILES; ++tile) {
        const int base = tile * TILE;
        // stage 64 candidate rows fp32 -> bf16 (4 uint4 per thread)
        #pragma unroll
        for (int k = 0; k < 4; ++k) {
            int idx = t + (k << 8);
            int row = idx >> 4, q4 = idx & 15;
            float4 f0 = E4[(size_t)(base + row) * (DIM / 4) + 2 * q4];
            float4 f1 = E4[(size_t)(base + row) * (DIM / 4) + 2 * q4 + 1];
            uint4 w;
            w.x = pack_bf(f0.x, f0.y); w.y = pack_bf(f0.z, f0.w);
            w.z = pack_bf(f1.x, f1.y); w.w = pack_bf(f1.z, f1.w);
            *(uint4*)&s_cand[row][q4 << 2] = w;
        }
        __syncthreads();

        __nv_bfloat162 z = __float2bfloat162_rn(0.f);
        __nv_bfloat162 a00x = z, a00y = z, a00z = z, a00w = z;
        __nv_bfloat162 a01x = z, a01y = z, a01z = z, a01w = z;
        __nv_bfloat162 a10x = z, a10y = z, a10z = z, a10w = z;
        __nv_bfloat162 a11x = z, a11y = z, a11z = z, a11w = z;
        #pragma unroll
        for (int i = 0; i < 16; ++i) {
            uint4 av0 = *(const uint4*)&c0r[i << 2];
            uint4 av1 = *(const uint4*)&c1r[i << 2];
            uint4 bv0 = *(const uint4*)&q0r[i << 2];
            uint4 bv1 = *(const uint4*)&q1r[i << 2];
            a00x = __hfma2(u2b(av0.x), u2b(bv0.x), a00x);
            a00y = __hfma2(u2b(av0.y), u2b(bv0.y), a00y);
            a00z = __hfma2(u2b(av0.z), u2b(bv0.z), a00z);
            a00w = __hfma2(u2b(av0.w), u2b(bv0.w), a00w);
            a01x = __hfma2(u2b(av0.x), u2b(bv1.x), a01x);
            a01y = __hfma2(u2b(av0.y), u2b(bv1.y), a01y);
            a01z = __hfma2(u2b(av0.z), u2b(bv1.z), a01z);
            a01w = __hfma2(u2b(av0.w), u2b(bv1.w), a01w);
            a10x = __hfma2(u2b(av1.x), u2b(bv0.x), a10x);
            a10y = __hfma2(u2b(av1.y), u2b(bv0.y), a10y);
            a10z = __hfma2(u2b(av1.z), u2b(bv0.z), a10z);
            a10w = __hfma2(u2b(av1.w), u2b(bv0.w), a10w);
            a11x = __hfma2(u2b(av1.x), u2b(bv1.x), a11x);
            a11y = __hfma2(u2b(av1.y), u2b(bv1.y), a11y);
            a11z = __hfma2(u2b(av1.z), u2b(bv1.z), a11z);
            a11w = __hfma2(u2b(av1.w), u2b(bv1.w), a11w);
        }
        float d00 = bsum(a00x, a00y, a00z, a00w);
        float d01 = bsum(a01x, a01y, a01z, a01w);
        float d10 = bsum(a10x, a10y, a10z, a10w);
        float d11 = bsum(a11x, a11y, a11z, a11w);
        cnt_q0 += (d00 >= scr_thr) + (d10 >= scr_thr);
        cnt_q1 += (d01 >= scr_thr) + (d11 >= scr_thr);
        __syncthreads();                     // compute done before restage
    }

    // ---- aggregate counts: lanes with equal (lane&3) share the query pair ----
    #pragma unroll
    for (int o = 4; o <= 16; o <<= 1) {
        cnt_q0 += __shfl_xor_sync(0xffffffffu, cnt_q0, o);
        cnt_q1 += __shfl_xor_sync(0xffffffffu, cnt_q1, o);
    }
    if (lane < 4) {
        if (cnt_q0) atomicAdd(&s_qcnt[qg + 2 * lane], cnt_q0);
        if (cnt_q1) atomicAdd(&s_qcnt[qg + 2 * lane + 1], cnt_q1);
    }
    __syncthreads();

    // ---- per-warp contributions: warp w -> queries 2w, 2w+1 ----
    float contrib = 0.0f;
    #pragma unroll
    for (int j = 0; j < 2; ++j) {
        const int q = 2 * wid + j;
        const float D = s_D[q];
        if (s_qcnt[q] >= K_NEG) {
            contrib += (float)K_NEG * fmaxf(D - sq_min, 0.0f);
        } else {
            // exact fp32 fallback: top-75 largest (prod, -idx), lexicographic
            const float* qp = emb + (size_t)s_qrow[q] * DIM;
            float prevP = INFINITY; int prevI = -1;
            for (int pick = 0; pick < K_NEG; ++pick) {
                float bp = -INFINITY; int bi = 0x7fffffff;
                for (int n = lane; n < N_NODES; n += 32) {
                    const float* e = emb + (size_t)n * DIM;
                    float p = -qp[0] * e[0];
                    #pragma unroll 8
                    for (int d = 1; d < DIM; ++d) p += qp[d] * e[d];
                    bool after = (p < prevP) || (p == prevP && n > prevI);
                    if (after && (p > bp || (p == bp && n < bi))) { bp = p; bi = n; }
                }
                #pragma unroll
                for (int o = 16; o; o >>= 1) {
                    float op = __shfl_xor_sync(0xffffffffu, bp, o);
                    int   oi = __shfl_xor_sync(0xffffffffu, bi, o);
                    if (op > bp || (op == bp && oi < bi)) { bp = op; bi = oi; }
                }
                prevP = bp; prevI = bi;
                float t2 = fmaxf(-bp * c, thr_theta);
                float a2 = acoshf(t2);
                float sq = fminf(K * a2 * a2, MAXSQ);
                contrib += fmaxf(D - sq, 0.0f);
            }
        }
    }

    if (lane == 0) s_wsum[wid] = contrib;
    __syncthreads();

    // ---- block sum -> partial, last-block-done final reduction ----
    if (t == 0) {
        float bs = 0.0f;
        #pragma unroll
        for (int w = 0; w < 8; ++w) bs += s_wsum[w];
        g_partial[bid] = bs;
        __threadfence();
        unsigned old = atomicInc(&g_ticket, NB - 1);  // wraps to 0 for replays
        s_islast = (old == NB - 1);
    }
    __syncthreads();

    if (s_islast) {
        float s = 0.0f;
        for (int i = t; i < NB; i += 256) s += g_partial[i];
        s_red[t] = s;
        __syncthreads();
        #pragma unroll
        for (int o = 128; o; o >>= 1) {
            if (t < o) s_red[t] += s_red[t + o];
            __syncthreads();
        }
        if (t == 0)
            out[0] = s_red[0] / (2.0f * (float)K_NEG * (float)T_LINKS);
    }
}

extern "C" void kernel_launch(void* const* d_in, const int* in_sizes, int n_in,
                              void* d_out, int out_size) {
    const float* emb   = (const float*)d_in[0];
    const float* cptr  = (const float*)d_in[1];
    const void*  links = d_in[2];

    fused_kernel<<<NB, 256>>>(emb, cptr, links, (float*)d_out);
}